// round 1
// baseline (speedup 1.0000x reference)
#include <cuda_runtime.h>

// GCN fused kernel: per-sentence tile (64 rows), fp32, packed f32x2 FMA.
// Problem: BNK=1280, L=64, DIN=512, DOUT=256, NREL=40, M=81920.
//
// out[m,:] = relu( (P_in[head(m)] + b_in[lab]) * w_in + P_self[m] * w_self ) * mask
//   P_in   = rep @ W_in,  P_self = rep @ W_self
//   w_in   = sigmoid(g_in[head(m)] + b_gate_in[lab]) * adj_mask_in^2
//   w_self = sigmoid(g_self[m]) * adj_mask_loop^2
// head(m) is within the same 64-row sentence block -> fully fused per CTA.

#define BNK_ 1280
#define L_ 64
#define DIN_ 512
#define DOUT_ 256
#define TK_ 32

typedef unsigned long long u64;

__device__ __forceinline__ u64 ffma2(u64 a, u64 b, u64 c) {
    u64 d;
    asm("fma.rn.f32x2 %0, %1, %2, %3;" : "=l"(d) : "l"(a), "l"(b), "l"(c));
    return d;
}
__device__ __forceinline__ u64 dup2(float x) {
    u64 d;
    asm("mov.b64 %0, {%1, %1};" : "=l"(d) : "f"(x));
    return d;
}
__device__ __forceinline__ u64 pack2(float lo, float hi) {
    u64 d;
    asm("mov.b64 %0, {%1, %2};" : "=l"(d) : "f"(lo), "f"(hi));
    return d;
}
__device__ __forceinline__ float2 asf2(u64 v) {
    union { u64 u; float2 f; } x;
    x.u = v;
    return x.f;
}

// SMEM layout (floats):
//   As   [64][TK]      : rep tile (row-major)             2048
//   Bs   [TK][256]     : W tile                           8192
//   Pin  [64][256]     : P_in tile                       16384
//   gin  [64], gsf[64] : gate accumulators                 128
#define SMEM_FLOATS (64 * TK_ + TK_ * 256 + 64 * 256 + 128)
#define SMEM_BYTES (SMEM_FLOATS * 4)

extern "C" __global__ void __launch_bounds__(256, 2)
gcn_fused(const float* __restrict__ rep,
          const float* __restrict__ adj_mask_in,
          const float* __restrict__ adj_mask_loop,
          const float* __restrict__ mask,
          const float* __restrict__ W_in,
          const float* __restrict__ b_in,
          const float* __restrict__ Wg_in,
          const float* __restrict__ bg_in,
          const float* __restrict__ W_self,
          const float* __restrict__ Wg_self,
          const int* __restrict__ arc,
          const int* __restrict__ lab,
          float* __restrict__ out)
{
    extern __shared__ float smf[];
    float* As  = smf;                    // [64][TK]
    float* Bs  = As + 64 * TK_;          // [TK][256]
    float* Pin = Bs + TK_ * 256;         // [64][256]
    float* gin = Pin + 64 * 256;         // [64]
    float* gsf = gin + 64;               // [64]

    const int tid = threadIdx.x;
    const int tx = tid & 15;             // column group owner
    const int ty = tid >> 4;             // row group owner
    const int r0 = ty * 4;               // 4 rows per thread
    const int c0 = tx * 4;               // cols c0 + 64*j, j=0..3
    const int m0 = blockIdx.x * L_;      // sentence base row

    // ---------------- gate pre-pass (also warms rep tile into L2/L1) --------
    {
        int row = tid >> 2;              // 0..63
        int part = tid & 3;              // quarter of K
        const float4* rp = reinterpret_cast<const float4*>(
            rep + (size_t)(m0 + row) * DIN_ + part * 128);
        const float4* gi = reinterpret_cast<const float4*>(Wg_in + part * 128);
        const float4* gs = reinterpret_cast<const float4*>(Wg_self + part * 128);
        float ai = 0.f, asf = 0.f;
#pragma unroll 8
        for (int q = 0; q < 32; q++) {
            float4 v = rp[q];
            float4 wi = gi[q];
            float4 ws = gs[q];
            ai  += v.x * wi.x + v.y * wi.y + v.z * wi.z + v.w * wi.w;
            asf += v.x * ws.x + v.y * ws.y + v.z * ws.z + v.w * ws.w;
        }
        // reduce across the 4 parts (lanes row*4+part are contiguous, aligned)
        ai  += __shfl_xor_sync(0xffffffffu, ai, 1);
        ai  += __shfl_xor_sync(0xffffffffu, ai, 2);
        asf += __shfl_xor_sync(0xffffffffu, asf, 1);
        asf += __shfl_xor_sync(0xffffffffu, asf, 2);
        if (part == 0) { gin[row] = ai; gsf[row] = asf; }
    }

    u64 acc[4][8];  // [row i][col pair: j*2+p] packed f32x2 accumulators

    // ---------------- two GEMM phases: P_in then P_self ---------------------
#pragma unroll 1
    for (int phase = 0; phase < 2; phase++) {
        const float* W = phase ? W_self : W_in;
#pragma unroll
        for (int i = 0; i < 4; i++)
#pragma unroll
            for (int p = 0; p < 8; p++) acc[i][p] = 0ull;

#pragma unroll 1
        for (int kt = 0; kt < DIN_; kt += TK_) {
            __syncthreads();  // previous chunk's compute done (or gate pass)
            // load As: 64 x TK, row-major, 512 float4 total
#pragma unroll
            for (int t = 0; t < 2; t++) {
                int i = tid + 256 * t;
                int row = i >> 3, kk = i & 7;
                float4 v = *reinterpret_cast<const float4*>(
                    rep + (size_t)(m0 + row) * DIN_ + kt + kk * 4);
                *reinterpret_cast<float4*>(&As[row * TK_ + kk * 4]) = v;
            }
            // load Bs: TK x 256, 2048 float4 total
#pragma unroll
            for (int t = 0; t < 8; t++) {
                int i = tid + 256 * t;
                int kq = i >> 6, c4 = i & 63;
                float4 v = *reinterpret_cast<const float4*>(
                    W + (size_t)(kt + kq) * DOUT_ + c4 * 4);
                *reinterpret_cast<float4*>(&Bs[kq * DOUT_ + c4 * 4]) = v;
            }
            __syncthreads();

#pragma unroll 2
            for (int k = 0; k < TK_; k += 4) {
                float av[4][4];
#pragma unroll
                for (int i = 0; i < 4; i++) {
                    float4 a4 = *reinterpret_cast<const float4*>(&As[(r0 + i) * TK_ + k]);
                    av[i][0] = a4.x; av[i][1] = a4.y; av[i][2] = a4.z; av[i][3] = a4.w;
                }
#pragma unroll
                for (int kk = 0; kk < 4; kk++) {
                    u64 ad[4];
#pragma unroll
                    for (int i = 0; i < 4; i++) ad[i] = dup2(av[i][kk]);
#pragma unroll
                    for (int j = 0; j < 4; j++) {
                        float4 b = *reinterpret_cast<const float4*>(
                            &Bs[(k + kk) * DOUT_ + c0 + 64 * j]);
                        u64 b0 = pack2(b.x, b.y);
                        u64 b1 = pack2(b.z, b.w);
#pragma unroll
                        for (int i = 0; i < 4; i++) {
                            acc[i][j * 2]     = ffma2(ad[i], b0, acc[i][j * 2]);
                            acc[i][j * 2 + 1] = ffma2(ad[i], b1, acc[i][j * 2 + 1]);
                        }
                    }
                }
            }
        }

        if (phase == 0) {
            // stash P_in tile in SMEM (each thread writes only its own cells;
            // visibility guaranteed by the syncthreads at the start of phase 1)
#pragma unroll
            for (int i = 0; i < 4; i++)
#pragma unroll
                for (int j = 0; j < 4; j++) {
                    float2 lo = asf2(acc[i][j * 2]);
                    float2 hi = asf2(acc[i][j * 2 + 1]);
                    float4 v = make_float4(lo.x, lo.y, hi.x, hi.y);
                    *reinterpret_cast<float4*>(&Pin[(r0 + i) * DOUT_ + c0 + 64 * j]) = v;
                }
        }
    }

    __syncthreads();  // Pin + gates fully visible

    // ---------------- combine: gather + gates + relu + store ----------------
#pragma unroll
    for (int i = 0; i < 4; i++) {
        int r = r0 + i;
        int m = m0 + r;
        int lr = lab[m];
        int g = (arc[2 * m] * L_ + arc[2 * m + 1]) - m0;
        g &= 63;  // guaranteed in-range by construction; clamp for safety
        float min_ = adj_mask_in[m];
        float mlp_ = adj_mask_loop[m];
        float win = (1.f / (1.f + expf(-(gin[g] + bg_in[lr])))) * min_ * min_;
        float wsf = (1.f / (1.f + expf(-gsf[r]))) * mlp_ * mlp_;
        float mk = mask[m];
#pragma unroll
        for (int j = 0; j < 4; j++) {
            int c = c0 + 64 * j;
            float2 lo = asf2(acc[i][j * 2]);
            float2 hi = asf2(acc[i][j * 2 + 1]);
            float4 p = *reinterpret_cast<const float4*>(&Pin[g * DOUT_ + c]);
            float4 bb = *reinterpret_cast<const float4*>(&b_in[lr * DOUT_ + c]);
            float4 o;
            o.x = fmaxf((p.x + bb.x) * win + lo.x * wsf, 0.f) * mk;
            o.y = fmaxf((p.y + bb.y) * win + lo.y * wsf, 0.f) * mk;
            o.z = fmaxf((p.z + bb.z) * win + hi.x * wsf, 0.f) * mk;
            o.w = fmaxf((p.w + bb.w) * win + hi.y * wsf, 0.f) * mk;
            *reinterpret_cast<float4*>(&out[(size_t)m * DOUT_ + c]) = o;
        }
    }
}

extern "C" void kernel_launch(void* const* d_in, const int* in_sizes, int n_in,
                              void* d_out, int out_size)
{
    (void)in_sizes; (void)n_in; (void)out_size;
    cudaFuncSetAttribute(gcn_fused, cudaFuncAttributeMaxDynamicSharedMemorySize,
                         SMEM_BYTES);
    gcn_fused<<<BNK_, 256, SMEM_BYTES>>>(
        (const float*)d_in[0],   // rep
        (const float*)d_in[1],   // adj_mask_in
        (const float*)d_in[2],   // adj_mask_loop
        (const float*)d_in[3],   // mask
        (const float*)d_in[4],   // W_in
        (const float*)d_in[5],   // b_in
        (const float*)d_in[6],   // W_gate_in
        (const float*)d_in[7],   // b_gate_in
        (const float*)d_in[8],   // W_self
        (const float*)d_in[9],   // W_gate_self
        (const int*)d_in[10],    // adj_arc_in
        (const int*)d_in[11],    // adj_lab_in
        (float*)d_out);
}